// round 1
// baseline (speedup 1.0000x reference)
#include <cuda_runtime.h>
#include <cstdint>

// Problem constants
constexpr int Cdim = 512;
constexpr int M    = 8 * 4096;   // B*L = 32768
constexpr int N    = 512;        // C_out
constexpr int KD   = 512;        // C_in (GEMM K)
constexpr int BM = 128, BN = 128, BK = 32;
constexpr int KIT = KD / BK;     // 16

// Shared memory layout (floats)
constexpr int PAD     = 36;               // 32 cols padded to 36 (conflict-free: 36 % 32 == 4)
constexpr int XS_ROWS = BM + 4;           // 132 rows (4-row halo for K=5 taps)
constexpr int XS_SZ   = XS_ROWS * PAD;    // 4752
constexpr int BS_SZ   = BN * PAD;         // 4608 per buffer
constexpr int AS_SZ   = BM * PAD;         // 4608
constexpr int WS_SZ   = 6 * 32;           // 5 taps + bias, per 32 k-cols
constexpr int SMEM_BYTES = (XS_SZ + 2 * BS_SZ + AS_SZ + WS_SZ) * 4 + BM * 4; // +nts

__device__ __forceinline__ uint32_t f2tf32(float x) {
    uint32_t r;
    asm("cvt.rna.tf32.f32 %0, %1;" : "=r"(r) : "f"(x));
    return r;
}

__device__ __forceinline__ void cpa16(float* dst, const float* src) {
    uint32_t s = (uint32_t)__cvta_generic_to_shared(dst);
    asm volatile("cp.async.cg.shared.global [%0], [%1], 16;" :: "r"(s), "l"(src));
}

__global__ void __launch_bounds__(256)
fused_dwconv_gemm(const float* __restrict__ x,     // [B,L,C]
                  const int*   __restrict__ segb,  // [B,S,2] int32
                  const float* __restrict__ wdw,   // [C,K]
                  const float* __restrict__ bdw,   // [C]
                  const float* __restrict__ wpw,   // [C_out,C_in]
                  const float* __restrict__ bpw,   // [C_out]
                  float*       __restrict__ out)   // [B,L,C_out]
{
    extern __shared__ float sm[];
    float* xs   = sm;                    // [132][36]  x halo tile
    float* bsm  = sm + XS_SZ;            // [2][128][36] B (w_pw) tiles
    float* asmv = bsm + 2 * BS_SZ;       // [128][36]  dw (A) tile
    float* ws   = asmv + AS_SZ;          // [6][32]    w_dw taps + b_dw
    int*   nts  = (int*)(ws + WS_SZ);    // [128]      valid tap count per row

    const int tid  = threadIdx.x;
    const int lane = tid & 31;
    const int warp = tid >> 5;
    const int wm   = (warp >> 2) * 64;   // warp m-offset (0 or 64)
    const int wn   = (warp & 3) * 32;    // warp n-offset
    const int bx   = blockIdx.x;
    const int m0   = (bx >> 2) * BM;     // N-tile fastest => 4 consecutive CTAs share x rows (L2)
    const int n0   = (bx & 3) * BN;

    // ---- per-row tap counts (once per CTA) ----
    if (tid < BM) {
        int m = m0 + tid;
        int l = m & 4095;
        const int* sp = segb + (m >> 12) * 16;   // [S][2]
        int ss = 0;                               // start of containing segment = max start <= l
        #pragma unroll
        for (int s = 1; s < 8; s++) {
            int st = sp[2 * s];
            if (st <= l && st > ss) ss = st;
        }
        int nt = l - ss + 1;
        nts[tid] = (nt > 5) ? 5 : nt;
    }

    auto load_tiles = [&](int it) {
        const int c0 = it * BK;
        // x halo: 132 rows x 32 cols  (clamped rows are never consumed: nt masks them)
        for (int idx = tid; idx < XS_ROWS * 8; idx += 256) {
            int row = idx >> 3, c4 = (idx & 7) << 2;
            int m = m0 - 4 + row;
            if (m < 0) m = 0;
            cpa16(xs + row * PAD + c4, x + m * Cdim + c0 + c4);
        }
        // B tile: w_pw[n0+row][c0..c0+31], 128 x 32
        float* bd = bsm + (it & 1) * BS_SZ;
        #pragma unroll
        for (int q = 0; q < 4; q++) {
            int idx = tid + q * 256;
            int row = idx >> 3, c4 = (idx & 7) << 2;
            cpa16(bd + row * PAD + c4, wpw + (n0 + row) * Cdim + c0 + c4);
        }
        // depthwise weights + bias for this k-slab (tiny; plain ld/st)
        if (tid < 192) {
            int j = tid >> 5, kk = tid & 31;
            ws[j * 32 + kk] = (j < 5) ? wdw[(c0 + kk) * 5 + j] : bdw[c0 + kk];
        }
        asm volatile("cp.async.commit_group;" ::: "memory");
    };

    // dw[r][kk] = b_dw + sum_{d<nt[r]} w_dw[:,4-d] * x[r+4-d]
    auto compute_dw = [&]() {
        const int kk0 = (tid & 7) << 2;
        const int rb  = tid >> 3;  // 0..31
        const float4 bv  = *(const float4*)(ws + 5 * 32 + kk0);
        const float4 wv0 = *(const float4*)(ws + 0 * 32 + kk0);
        const float4 wv1 = *(const float4*)(ws + 1 * 32 + kk0);
        const float4 wv2 = *(const float4*)(ws + 2 * 32 + kk0);
        const float4 wv3 = *(const float4*)(ws + 3 * 32 + kk0);
        const float4 wv4 = *(const float4*)(ws + 4 * 32 + kk0);
        #pragma unroll
        for (int pass = 0; pass < 4; pass++) {
            int r = pass * 32 + rb;
            int ntr = nts[r];
            float4 acc = bv;
            {   // d = 0 always valid (nt >= 1)
                float4 xv = *(const float4*)(xs + (r + 4) * PAD + kk0);
                acc.x += wv4.x * xv.x; acc.y += wv4.y * xv.y;
                acc.z += wv4.z * xv.z; acc.w += wv4.w * xv.w;
            }
            if (ntr > 1) {
                float4 xv = *(const float4*)(xs + (r + 3) * PAD + kk0);
                acc.x += wv3.x * xv.x; acc.y += wv3.y * xv.y;
                acc.z += wv3.z * xv.z; acc.w += wv3.w * xv.w;
            }
            if (ntr > 2) {
                float4 xv = *(const float4*)(xs + (r + 2) * PAD + kk0);
                acc.x += wv2.x * xv.x; acc.y += wv2.y * xv.y;
                acc.z += wv2.z * xv.z; acc.w += wv2.w * xv.w;
            }
            if (ntr > 3) {
                float4 xv = *(const float4*)(xs + (r + 1) * PAD + kk0);
                acc.x += wv1.x * xv.x; acc.y += wv1.y * xv.y;
                acc.z += wv1.z * xv.z; acc.w += wv1.w * xv.w;
            }
            if (ntr > 4) {
                float4 xv = *(const float4*)(xs + r * PAD + kk0);
                acc.x += wv0.x * xv.x; acc.y += wv0.y * xv.y;
                acc.z += wv0.z * xv.z; acc.w += wv0.w * xv.w;
            }
            *(float4*)(asmv + r * PAD + kk0) = acc;
        }
    };

    float cacc[4][4][4];
    #pragma unroll
    for (int i = 0; i < 4; i++)
        #pragma unroll
        for (int j = 0; j < 4; j++)
            #pragma unroll
            for (int k = 0; k < 4; k++) cacc[i][j][k] = 0.f;

    auto mma_stage = [&](const float* bbuf) {
        #pragma unroll
        for (int ks = 0; ks < 4; ks++) {
            uint32_t af[4][4], bf[4][2];
            const int ac = ks * 8 + (lane & 3);
            const int ar = wm + (lane >> 2);
            #pragma unroll
            for (int mt = 0; mt < 4; mt++) {
                const float* ap = asmv + (ar + mt * 16) * PAD + ac;
                af[mt][0] = f2tf32(ap[0]);
                af[mt][1] = f2tf32(ap[8 * PAD]);
                af[mt][2] = f2tf32(ap[4]);
                af[mt][3] = f2tf32(ap[8 * PAD + 4]);
            }
            const int br = wn + (lane >> 2);
            #pragma unroll
            for (int nt8 = 0; nt8 < 4; nt8++) {
                const float* bp = bbuf + (br + nt8 * 8) * PAD + ac;
                bf[nt8][0] = f2tf32(bp[0]);
                bf[nt8][1] = f2tf32(bp[4]);
            }
            #pragma unroll
            for (int mt = 0; mt < 4; mt++)
                #pragma unroll
                for (int nt8 = 0; nt8 < 4; nt8++) {
                    float* c = cacc[mt][nt8];
                    asm volatile(
                        "mma.sync.aligned.m16n8k8.row.col.f32.tf32.tf32.f32 "
                        "{%0,%1,%2,%3},{%4,%5,%6,%7},{%8,%9},{%0,%1,%2,%3};"
                        : "+f"(c[0]), "+f"(c[1]), "+f"(c[2]), "+f"(c[3])
                        : "r"(af[mt][0]), "r"(af[mt][1]), "r"(af[mt][2]), "r"(af[mt][3]),
                          "r"(bf[nt8][0]), "r"(bf[nt8][1]));
                }
        }
    };

    // ---- pipeline ----
    load_tiles(0);
    asm volatile("cp.async.wait_group 0;" ::: "memory");
    __syncthreads();            // nts + ws + tiles visible
    compute_dw();
    __syncthreads();

    #pragma unroll 1
    for (int it = 0; it < KIT; it++) {
        if (it + 1 < KIT) load_tiles(it + 1);     // async loads overlap MMA below
        mma_stage(bsm + (it & 1) * BS_SZ);
        if (it + 1 < KIT) {
            asm volatile("cp.async.wait_group 0;" ::: "memory");
            __syncthreads();    // all warps done with asmv; new xs/ws/B visible
            compute_dw();
            __syncthreads();
        }
    }

    // ---- epilogue: + b_pw, write out ----
    float2* outv = (float2*)out;
    #pragma unroll
    for (int nt8 = 0; nt8 < 4; nt8++) {
        int gn = n0 + wn + nt8 * 8 + (lane & 3) * 2;
        float2 bp = *(const float2*)(bpw + gn);
        #pragma unroll
        for (int mt = 0; mt < 4; mt++) {
            int gm = m0 + wm + mt * 16 + (lane >> 2);
            float2 v0 = { cacc[mt][nt8][0] + bp.x, cacc[mt][nt8][1] + bp.y };
            float2 v1 = { cacc[mt][nt8][2] + bp.x, cacc[mt][nt8][3] + bp.y };
            outv[(gm * N + gn) >> 1]       = v0;
            outv[((gm + 8) * N + gn) >> 1] = v1;
        }
    }
}

extern "C" void kernel_launch(void* const* d_in, const int* in_sizes, int n_in,
                              void* d_out, int out_size) {
    const float* x    = (const float*)d_in[0];
    const int*   segb = (const int*)  d_in[1];
    const float* wdw  = (const float*)d_in[2];
    const float* bdw  = (const float*)d_in[3];
    const float* wpw  = (const float*)d_in[4];
    const float* bpw  = (const float*)d_in[5];
    float* out = (float*)d_out;

    cudaFuncSetAttribute(fused_dwconv_gemm,
                         cudaFuncAttributeMaxDynamicSharedMemorySize, SMEM_BYTES);
    dim3 grid((M / BM) * (N / BN));   // 1024 CTAs, N-tile fastest
    fused_dwconv_gemm<<<grid, 256, SMEM_BYTES>>>(x, segb, wdw, bdw, wpw, bpw, out);
}

// round 3
// speedup vs baseline: 1.2344x; 1.2344x over previous
#include <cuda_runtime.h>
#include <cuda_fp16.h>
#include <cstdint>

// ---------------- problem constants ----------------
constexpr int Cdim = 512;          // channels (GEMM K and N)
constexpr int BM = 128, BN = 128, BK = 32;
constexpr int KIT = Cdim / BK;     // 16 k-slabs

// ---------------- smem layout (bytes) ----------------
constexpr int NTS_OFF = 0;                       // 128 ints
constexpr int WS_OFF  = 512;                     // 2 x 192 floats (taps+bias)
constexpr int XS_OFF  = 2048;                    // 2 x 132x36 floats (x halo)
constexpr int XS_STRF = 36;
constexpr int XS_BUFF = 132 * XS_STRF;
constexpr int AB_STR  = 80;                      // 32 halves + 8 pad (conflict-free)
constexpr int A_OFF   = 40064;                   // 2 x 128x80 B (fp16 A)
constexpr int A_BUFB  = 128 * AB_STR;
constexpr int B_OFF   = 60544;                   // 4 x 128x80 B (fp16 B)
constexpr int B_BUFB  = 128 * AB_STR;
constexpr int SMEM_BYTES = B_OFF + 4 * B_BUFB;   // 101504

// fp16 copy of w_pw, built once per launch
__device__ __half g_wpwh[Cdim * Cdim];

// ---------------- helpers ----------------
static __device__ __forceinline__ uint32_t smem_u32(const void* p) {
    uint32_t a;
    asm("{ .reg .u64 t; cvta.to.shared.u64 t, %1; cvt.u32.u64 %0, t; }" : "=r"(a) : "l"(p));
    return a;
}
static __device__ __forceinline__ void cpa16(void* dst, const void* src) {
    uint32_t s = smem_u32(dst);
    asm volatile("cp.async.cg.shared.global [%0], [%1], 16;" :: "r"(s), "l"(src));
}
static __device__ __forceinline__ void ldmx4(uint32_t* r, uint32_t a) {
    asm volatile("ldmatrix.sync.aligned.m8n8.x4.shared.b16 {%0,%1,%2,%3}, [%4];"
                 : "=r"(r[0]), "=r"(r[1]), "=r"(r[2]), "=r"(r[3]) : "r"(a));
}
static __device__ __forceinline__ void hmma(float* c, const uint32_t* a,
                                            uint32_t b0, uint32_t b1) {
    asm volatile(
        "mma.sync.aligned.m16n8k16.row.col.f32.f16.f16.f32 "
        "{%0,%1,%2,%3},{%4,%5,%6,%7},{%8,%9},{%0,%1,%2,%3};"
        : "+f"(c[0]), "+f"(c[1]), "+f"(c[2]), "+f"(c[3])
        : "r"(a[0]), "r"(a[1]), "r"(a[2]), "r"(a[3]), "r"(b0), "r"(b1));
}

// ---------------- pre-kernel: w_pw fp32 -> fp16 ----------------
__global__ void cvt_wpw_k(const float4* __restrict__ w) {
    int i = blockIdx.x * 256 + threadIdx.x;
    float4 v = w[i];
    __half2 h0 = __floats2half2_rn(v.x, v.y);
    __half2 h1 = __floats2half2_rn(v.z, v.w);
    uint2 u;
    u.x = *reinterpret_cast<uint32_t*>(&h0);
    u.y = *reinterpret_cast<uint32_t*>(&h1);
    *reinterpret_cast<uint2*>(g_wpwh + (size_t)i * 4) = u;
}

// ---------------- main fused kernel ----------------
__global__ void __launch_bounds__(256, 2)
fused_dw_hmma(const float* __restrict__ x,     // [B,L,C]
              const int*   __restrict__ segb,  // [B,S,2]
              const float* __restrict__ wdw,   // [C,K]
              const float* __restrict__ bdw,   // [C]
              const float* __restrict__ bpw,   // [C]
              float*       __restrict__ out)   // [B,L,C]
{
    extern __shared__ char sm[];
    const uint32_t smb = smem_u32(sm);
    int*   nts    = (int*)(sm + NTS_OFF);
    float* ws_all = (float*)(sm + WS_OFF);
    float* xs_all = (float*)(sm + XS_OFF);

    const int tid  = threadIdx.x;
    const int lane = tid & 31;
    const int warp = tid >> 5;
    const int wm   = (warp >> 2) * 64;
    const int wn   = (warp & 3) * 32;
    const int bx   = blockIdx.x;
    const int m0   = (bx >> 2) * BM;   // N-tile fastest: 4 CTAs share x rows via L2
    const int n0   = (bx & 3) * BN;

    // per-row valid tap counts
    if (tid < BM) {
        int m = m0 + tid;
        int l = m & 4095;
        const int* sp = segb + (m >> 12) * 16;
        int ss = 0;
        #pragma unroll
        for (int s = 1; s < 8; s++) {
            int st = sp[2 * s];
            if (st <= l && st > ss) ss = st;
        }
        int nt = l - ss + 1;
        nts[tid] = (nt > 5) ? 5 : nt;
    }

    auto load_tiles = [&](int s) {
        if (s >= KIT) return;
        const int c0 = s * BK;
        // x halo: 132 rows x 32 floats
        float* xd = xs_all + (s & 1) * XS_BUFF;
        for (int idx = tid; idx < 132 * 8; idx += 256) {
            int row = idx >> 3, ch = idx & 7;
            int m = m0 - 4 + row; if (m < 0) m = 0;
            cpa16(xd + row * XS_STRF + ch * 4, x + (size_t)m * Cdim + c0 + ch * 4);
        }
        // B tile: 128 rows x 32 halves (64B data, 80B stride)
        char* bd = sm + B_OFF + (s & 3) * B_BUFB;
        #pragma unroll
        for (int q = 0; q < 2; q++) {
            int idx = tid + q * 256;
            int row = idx >> 2, ch = idx & 3;
            cpa16(bd + row * AB_STR + ch * 16,
                  g_wpwh + (size_t)(n0 + row) * Cdim + c0 + ch * 8);
        }
        // dw taps + bias (plain stores; visible after barrier)
        if (tid < 192) {
            int j = tid >> 5, kk = tid & 31;
            ws_all[(s & 1) * 192 + j * 32 + kk] =
                (j < 5) ? wdw[(c0 + kk) * 5 + j] : bdw[c0 + kk];
        }
    };

    // dw conv (fp32) -> fp16 A tile
    auto compute_dw = [&](int it) {
        const float* xsb = xs_all + (it & 1) * XS_BUFF;
        const float* wsb = ws_all + (it & 1) * 192;
        char* Ab = sm + A_OFF + (it & 1) * A_BUFB;
        const int p = tid >> 3;
        const int kk0 = (tid & 7) << 2;
        const float4 w0 = *(const float4*)(wsb + 0 * 32 + kk0);
        const float4 w1 = *(const float4*)(wsb + 1 * 32 + kk0);
        const float4 w2 = *(const float4*)(wsb + 2 * 32 + kk0);
        const float4 w3 = *(const float4*)(wsb + 3 * 32 + kk0);
        const float4 w4 = *(const float4*)(wsb + 4 * 32 + kk0);
        const float4 bv = *(const float4*)(wsb + 5 * 32 + kk0);
        float4 v[8];
        #pragma unroll
        for (int j = 0; j < 8; j++)
            v[j] = *(const float4*)(xsb + (4 * p + j) * XS_STRF + kk0);
        #pragma unroll
        for (int j = 0; j < 4; j++) {
            int r = 4 * p + j;
            int ntr = nts[r];
            float4 a = bv;
            a.x += w4.x * v[j+4].x; a.y += w4.y * v[j+4].y;
            a.z += w4.z * v[j+4].z; a.w += w4.w * v[j+4].w;
            if (ntr > 1) { a.x += w3.x * v[j+3].x; a.y += w3.y * v[j+3].y;
                           a.z += w3.z * v[j+3].z; a.w += w3.w * v[j+3].w; }
            if (ntr > 2) { a.x += w2.x * v[j+2].x; a.y += w2.y * v[j+2].y;
                           a.z += w2.z * v[j+2].z; a.w += w2.w * v[j+2].w; }
            if (ntr > 3) { a.x += w1.x * v[j+1].x; a.y += w1.y * v[j+1].y;
                           a.z += w1.z * v[j+1].z; a.w += w1.w * v[j+1].w; }
            if (ntr > 4) { a.x += w0.x * v[j+0].x; a.y += w0.y * v[j+0].y;
                           a.z += w0.z * v[j+0].z; a.w += w0.w * v[j+0].w; }
            __half2 h0 = __floats2half2_rn(a.x, a.y);
            __half2 h1 = __floats2half2_rn(a.z, a.w);
            uint2 u;
            u.x = *reinterpret_cast<uint32_t*>(&h0);
            u.y = *reinterpret_cast<uint32_t*>(&h1);
            *reinterpret_cast<uint2*>(Ab + r * AB_STR + kk0 * 2) = u;
        }
    };

    float cacc[4][4][4];
    #pragma unroll
    for (int i = 0; i < 4; i++)
        #pragma unroll
        for (int j = 0; j < 4; j++)
            #pragma unroll
            for (int k = 0; k < 4; k++) cacc[i][j][k] = 0.f;

    auto mma_stage = [&](int it) {
        const uint32_t Ab = smb + A_OFF + (it & 1) * A_BUFB;
        const uint32_t Bb = smb + B_OFF + (it & 3) * B_BUFB;
        // A: lanes 0-7 rows 0-7 klo | 8-15 rows 8-15 klo | 16-23 rows 0-7 khi | 24-31 rows 8-15 khi
        const uint32_t aaddr = Ab + (wm + (lane & 15)) * AB_STR + (lane >> 4) * 16;
        // B: m0=(n0-7,klo) m1=(n0-7,khi) m2=(n8-15,klo) m3=(n8-15,khi)
        const uint32_t baddr = Bb + (wn + (lane & 7) + ((lane >> 4) & 1) * 8) * AB_STR
                             + ((lane >> 3) & 1) * 16;
        #pragma unroll
        for (int ks = 0; ks < 2; ks++) {
            uint32_t af[4][4], bf[2][4];
            #pragma unroll
            for (int mt = 0; mt < 4; mt++)
                ldmx4(af[mt], aaddr + mt * 16 * AB_STR + ks * 32);
            #pragma unroll
            for (int g = 0; g < 2; g++)
                ldmx4(bf[g], baddr + g * 16 * AB_STR + ks * 32);
            #pragma unroll
            for (int mt = 0; mt < 4; mt++)
                #pragma unroll
                for (int nt = 0; nt < 4; nt++)
                    hmma(cacc[mt][nt], af[mt],
                         bf[nt >> 1][(nt & 1) * 2 + 0],
                         bf[nt >> 1][(nt & 1) * 2 + 1]);
        }
    };

    // ---- pipeline: loads 2 slabs ahead, A double-buffered ----
    load_tiles(0); asm volatile("cp.async.commit_group;" ::: "memory");
    load_tiles(1); asm volatile("cp.async.commit_group;" ::: "memory");
    asm volatile("cp.async.wait_group 1;" ::: "memory");
    __syncthreads();
    compute_dw(0);
    __syncthreads();

    #pragma unroll 1
    for (int it = 0; it < KIT; it++) {
        load_tiles(it + 2);
        asm volatile("cp.async.commit_group;" ::: "memory");
        mma_stage(it);
        if (it + 1 < KIT) {
            asm volatile("cp.async.wait_group 1;" ::: "memory");
            __syncthreads();                 // slab it+1 gmem data landed
            compute_dw(it + 1);
            __syncthreads();                 // A[(it+1)&1] visible to all warps
        }
    }

    // ---- epilogue: + b_pw, coalesced float2 stores ----
    float2* outv = (float2*)out;
    #pragma unroll
    for (int nt = 0; nt < 4; nt++) {
        int gn = n0 + wn + nt * 8 + (lane & 3) * 2;
        float2 bp = *(const float2*)(bpw + gn);
        #pragma unroll
        for (int mt = 0; mt < 4; mt++) {
            int gm = m0 + wm + mt * 16 + (lane >> 2);
            float2 v0 = { cacc[mt][nt][0] + bp.x, cacc[mt][nt][1] + bp.y };
            float2 v1 = { cacc[mt][nt][2] + bp.x, cacc[mt][nt][3] + bp.y };
            outv[((size_t)gm * Cdim + gn) >> 1]       = v0;
            outv[(((size_t)gm + 8) * Cdim + gn) >> 1] = v1;
        }
    }
}

extern "C" void kernel_launch(void* const* d_in, const int* in_sizes, int n_in,
                              void* d_out, int out_size) {
    const float* x    = (const float*)d_in[0];
    const int*   segb = (const int*)  d_in[1];
    const float* wdw  = (const float*)d_in[2];
    const float* bdw  = (const float*)d_in[3];
    const float* wpw  = (const float*)d_in[4];
    const float* bpw  = (const float*)d_in[5];
    float* out = (float*)d_out;

    cvt_wpw_k<<<Cdim * Cdim / 4 / 256, 256>>>((const float4*)wpw);

    cudaFuncSetAttribute(fused_dw_hmma,
                         cudaFuncAttributeMaxDynamicSharedMemorySize, SMEM_BYTES);
    dim3 grid((32768 / BM) * (Cdim / BN));   // 1024 CTAs
    fused_dw_hmma<<<grid, 256, SMEM_BYTES>>>(x, segb, wdw, bdw, bpw, out);
}

// round 4
// speedup vs baseline: 1.5013x; 1.2162x over previous
#include <cuda_runtime.h>
#include <cuda_fp16.h>
#include <cstdint>

// ---------------- problem constants ----------------
constexpr int Cdim = 512;          // channels (GEMM K and N)
constexpr int BM = 128, BN = 128, BK = 32;
constexpr int KIT = Cdim / BK;     // 16 k-slabs

// ---------------- smem layout (bytes) ----------------
constexpr int NTS_OFF = 0;                         // 128 ints
constexpr int WS_OFF  = 512;                       // 3 x 768 B (taps+bias per slab)
constexpr int XS_OFF  = 2816;                      // 3 x 132x32 floats (x halo, 128B rows)
constexpr int XS_BUFB = 132 * 128;                 // 16896
constexpr int AB_STR  = 80;                        // 32 halves + 8 pad (ldmatrix conflict-free)
constexpr int A_OFF   = XS_OFF + 3 * XS_BUFB;      // 53504
constexpr int AB_BUFB = 128 * AB_STR;              // 10240
constexpr int B_OFF   = A_OFF + 3 * AB_BUFB;       // 84224
constexpr int SMEM_BYTES = B_OFF + 3 * AB_BUFB;    // 114944  (2 CTAs/SM: 229888 <= 233472)

// fp16 copy of w_pw + reorganized dw taps, built once per launch
__device__ __half g_wpwh[Cdim * Cdim];
__device__ float  g_wtap[KIT * 192];               // [slab][6][32]: taps 0..4 + bias

// ---------------- helpers ----------------
static __device__ __forceinline__ uint32_t smem_u32(const void* p) {
    uint32_t a;
    asm("{ .reg .u64 t; cvta.to.shared.u64 t, %1; cvt.u32.u64 %0, t; }" : "=r"(a) : "l"(p));
    return a;
}
static __device__ __forceinline__ void cpa16(void* dst, const void* src) {
    uint32_t s = smem_u32(dst);
    asm volatile("cp.async.cg.shared.global [%0], [%1], 16;" :: "r"(s), "l"(src));
}
static __device__ __forceinline__ void ldmx4(uint32_t* r, uint32_t a) {
    asm volatile("ldmatrix.sync.aligned.m8n8.x4.shared.b16 {%0,%1,%2,%3}, [%4];"
                 : "=r"(r[0]), "=r"(r[1]), "=r"(r[2]), "=r"(r[3]) : "r"(a));
}
static __device__ __forceinline__ void hmma(float* c, const uint32_t* a,
                                            uint32_t b0, uint32_t b1) {
    asm volatile(
        "mma.sync.aligned.m16n8k16.row.col.f32.f16.f16.f32 "
        "{%0,%1,%2,%3},{%4,%5,%6,%7},{%8,%9},{%0,%1,%2,%3};"
        : "+f"(c[0]), "+f"(c[1]), "+f"(c[2]), "+f"(c[3])
        : "r"(a[0]), "r"(a[1]), "r"(a[2]), "r"(a[3]), "r"(b0), "r"(b1));
}
#define COMMIT asm volatile("cp.async.commit_group;" ::: "memory")

// ---------------- pre-kernel: w_pw fp32->fp16, w_dw/b_dw reorg ----------------
__global__ void prep_k(const float4* __restrict__ wpw,
                       const float*  __restrict__ wdw,
                       const float*  __restrict__ bdw) {
    int bx = blockIdx.x;
    if (bx < 256) {
        int i = bx * 256 + threadIdx.x;
        float4 v = wpw[i];
        __half2 h0 = __floats2half2_rn(v.x, v.y);
        __half2 h1 = __floats2half2_rn(v.z, v.w);
        uint2 u;
        u.x = *reinterpret_cast<uint32_t*>(&h0);
        u.y = *reinterpret_cast<uint32_t*>(&h1);
        *reinterpret_cast<uint2*>(g_wpwh + (size_t)i * 4) = u;
    } else {
        int i = (bx - 256) * 256 + threadIdx.x;   // 0..3071
        if (i < KIT * 192) {
            int s = i / 192, r = i % 192, j = r >> 5, kk = r & 31;
            g_wtap[i] = (j < 5) ? wdw[(s * 32 + kk) * 5 + j] : bdw[s * 32 + kk];
        }
    }
}

// ---------------- main fused kernel ----------------
__global__ void __launch_bounds__(256, 2)
fused_dw_hmma(const float* __restrict__ x,     // [B,L,C]
              const int*   __restrict__ segb,  // [B,S,2]
              const float* __restrict__ bpw,   // [C]
              float*       __restrict__ out)   // [B,L,C]
{
    extern __shared__ char sm[];
    const uint32_t smb = smem_u32(sm);
    int*   nts    = (int*)(sm + NTS_OFF);
    float* ws_all = (float*)(sm + WS_OFF);

    const int tid  = threadIdx.x;
    const int lane = tid & 31;
    const int warp = tid >> 5;
    const int wm   = (warp >> 2) * 64;
    const int wn   = (warp & 3) * 32;
    const int bx   = blockIdx.x;
    const int m0   = (bx >> 2) * BM;   // N-tile fastest: 4 CTAs share x rows via L2
    const int n0   = (bx & 3) * BN;

    // per-row valid tap counts (visible after first barrier)
    if (tid < BM) {
        int m = m0 + tid;
        int l = m & 4095;
        const int* sp = segb + (m >> 12) * 16;
        int ss = 0;
        #pragma unroll
        for (int s = 1; s < 8; s++) {
            int st = sp[2 * s];
            if (st <= l && st > ss) ss = st;
        }
        int nt = l - ss + 1;
        nts[tid] = (nt > 5) ? 5 : nt;
    }

    // ---- loaders (cp.async only; caller commits) ----
    auto load_x = [&](int s) {                    // x halo + dw taps for slab s
        if (s >= KIT) return;
        const int c0 = s * BK;
        char* xd = sm + XS_OFF + (s % 3) * XS_BUFB;
        for (int idx = tid; idx < 132 * 8; idx += 256) {
            int row = idx >> 3, ch = idx & 7;
            int m = m0 - 4 + row; if (m < 0) m = 0;
            cpa16(xd + row * 128 + ch * 16, x + (size_t)m * Cdim + c0 + ch * 4);
        }
        if (tid < 48)
            cpa16((char*)ws_all + (s % 3) * 768 + tid * 16, g_wtap + s * 192 + tid * 4);
    };
    auto load_B = [&](int s) {                    // w_pw tile for slab s
        if (s >= KIT) return;
        const int c0 = s * BK;
        char* bd = sm + B_OFF + (s % 3) * AB_BUFB;
        #pragma unroll
        for (int q = 0; q < 2; q++) {
            int idx = tid + q * 256;
            int row = idx >> 2, ch = idx & 3;
            cpa16(bd + row * AB_STR + ch * 16,
                  g_wpwh + (size_t)(n0 + row) * Cdim + c0 + ch * 8);
        }
    };

    // dw conv (fp32) -> fp16 A tile for slab s
    auto compute_dw = [&](int s) {
        const float* xsb = (const float*)(sm + XS_OFF + (s % 3) * XS_BUFB);
        const float* wsb = ws_all + (s % 3) * 192;
        char* Ab = sm + A_OFF + (s % 3) * AB_BUFB;
        const int p = tid >> 3;
        const int kk0 = (tid & 7) << 2;
        const float4 w0 = *(const float4*)(wsb + 0 * 32 + kk0);
        const float4 w1 = *(const float4*)(wsb + 1 * 32 + kk0);
        const float4 w2 = *(const float4*)(wsb + 2 * 32 + kk0);
        const float4 w3 = *(const float4*)(wsb + 3 * 32 + kk0);
        const float4 w4 = *(const float4*)(wsb + 4 * 32 + kk0);
        const float4 bv = *(const float4*)(wsb + 5 * 32 + kk0);
        float4 v[8];
        #pragma unroll
        for (int j = 0; j < 8; j++)
            v[j] = *(const float4*)(xsb + (4 * p + j) * 32 + kk0);
        #pragma unroll
        for (int j = 0; j < 4; j++) {
            int r = 4 * p + j;
            int ntr = nts[r];
            float4 a = bv;
            a.x += w4.x * v[j+4].x; a.y += w4.y * v[j+4].y;
            a.z += w4.z * v[j+4].z; a.w += w4.w * v[j+4].w;
            if (ntr > 1) { a.x += w3.x * v[j+3].x; a.y += w3.y * v[j+3].y;
                           a.z += w3.z * v[j+3].z; a.w += w3.w * v[j+3].w; }
            if (ntr > 2) { a.x += w2.x * v[j+2].x; a.y += w2.y * v[j+2].y;
                           a.z += w2.z * v[j+2].z; a.w += w2.w * v[j+2].w; }
            if (ntr > 3) { a.x += w1.x * v[j+1].x; a.y += w1.y * v[j+1].y;
                           a.z += w1.z * v[j+1].z; a.w += w1.w * v[j+1].w; }
            if (ntr > 4) { a.x += w0.x * v[j+0].x; a.y += w0.y * v[j+0].y;
                           a.z += w0.z * v[j+0].z; a.w += w0.w * v[j+0].w; }
            __half2 h0 = __floats2half2_rn(a.x, a.y);
            __half2 h1 = __floats2half2_rn(a.z, a.w);
            uint2 u;
            u.x = *reinterpret_cast<uint32_t*>(&h0);
            u.y = *reinterpret_cast<uint32_t*>(&h1);
            *reinterpret_cast<uint2*>(Ab + r * AB_STR + kk0 * 2) = u;
        }
    };

    float cacc[4][4][4];
    #pragma unroll
    for (int i = 0; i < 4; i++)
        #pragma unroll
        for (int j = 0; j < 4; j++)
            #pragma unroll
            for (int k = 0; k < 4; k++) cacc[i][j][k] = 0.f;

    auto mma_stage = [&](int it) {
        const uint32_t Ab = smb + A_OFF + (it % 3) * AB_BUFB;
        const uint32_t Bb = smb + B_OFF + (it % 3) * AB_BUFB;
        const uint32_t aaddr = Ab + (wm + (lane & 15)) * AB_STR + (lane >> 4) * 16;
        const uint32_t baddr = Bb + (wn + (lane & 7) + ((lane >> 4) & 1) * 8) * AB_STR
                             + ((lane >> 3) & 1) * 16;
        #pragma unroll
        for (int ks = 0; ks < 2; ks++) {
            uint32_t af[4][4], bf[2][4];
            #pragma unroll
            for (int mt = 0; mt < 4; mt++)
                ldmx4(af[mt], aaddr + mt * 16 * AB_STR + ks * 32);
            #pragma unroll
            for (int g = 0; g < 2; g++)
                ldmx4(bf[g], baddr + g * 16 * AB_STR + ks * 32);
            #pragma unroll
            for (int mt = 0; mt < 4; mt++)
                #pragma unroll
                for (int nt = 0; nt < 4; nt++)
                    hmma(cacc[mt][nt], af[mt],
                         bf[nt >> 1][(nt & 1) * 2 + 0],
                         bf[nt >> 1][(nt & 1) * 2 + 1]);
        }
    };

    // ---- prologue: groups [x0][x1][x2][B0][B1]; dw(0), dw(1) ----
    load_x(0); COMMIT;
    load_x(1); COMMIT;
    load_x(2); COMMIT;
    load_B(0); COMMIT;
    load_B(1); COMMIT;
    asm volatile("cp.async.wait_group 3;" ::: "memory");   // x0,x1 landed
    __syncthreads();                                        // + nts visible
    compute_dw(0);
    compute_dw(1);

    // ---- main loop: ONE barrier per slab; mma(it) + dw(it+2) overlapped ----
    #pragma unroll 1
    for (int it = 0; it < KIT; it++) {
        // wait leaves only the newest group [B(it+1)] pending:
        // guarantees x(it+2), ws(it+2), B(it) landed.
        asm volatile("cp.async.wait_group 1;" ::: "memory");
        __syncthreads();          // visibility + A/B/x buffer recycling fence
        load_x(it + 3); COMMIT;   // empty commit past the end keeps accounting uniform
        load_B(it + 2); COMMIT;
        mma_stage(it);
        if (it + 2 < KIT) compute_dw(it + 2);
    }

    // ---- epilogue: + b_pw, coalesced float2 stores ----
    float2* outv = (float2*)out;
    #pragma unroll
    for (int nt = 0; nt < 4; nt++) {
        int gn = n0 + wn + nt * 8 + (lane & 3) * 2;
        float2 bp = *(const float2*)(bpw + gn);
        #pragma unroll
        for (int mt = 0; mt < 4; mt++) {
            int gm = m0 + wm + mt * 16 + (lane >> 2);
            float2 v0 = { cacc[mt][nt][0] + bp.x, cacc[mt][nt][1] + bp.y };
            float2 v1 = { cacc[mt][nt][2] + bp.x, cacc[mt][nt][3] + bp.y };
            outv[((size_t)gm * Cdim + gn) >> 1]       = v0;
            outv[(((size_t)gm + 8) * Cdim + gn) >> 1] = v1;
        }
    }
}

extern "C" void kernel_launch(void* const* d_in, const int* in_sizes, int n_in,
                              void* d_out, int out_size) {
    const float* x    = (const float*)d_in[0];
    const int*   segb = (const int*)  d_in[1];
    const float* wdw  = (const float*)d_in[2];
    const float* bdw  = (const float*)d_in[3];
    const float* wpw  = (const float*)d_in[4];
    const float* bpw  = (const float*)d_in[5];
    float* out = (float*)d_out;

    prep_k<<<268, 256>>>((const float4*)wpw, wdw, bdw);

    cudaFuncSetAttribute(fused_dw_hmma,
                         cudaFuncAttributeMaxDynamicSharedMemorySize, SMEM_BYTES);
    dim3 grid((32768 / BM) * (Cdim / BN));   // 1024 CTAs
    fused_dw_hmma<<<grid, 256, SMEM_BYTES>>>(x, segb, bpw, out);
}

// round 5
// speedup vs baseline: 1.9556x; 1.3026x over previous
#include <cuda_runtime.h>
#include <cuda_fp16.h>
#include <cstdint>

// ---------------- problem constants ----------------
constexpr int Cdim = 512;          // channels (GEMM K and N)
constexpr int Mrows = 32768;       // B*L
constexpr int BM = 128, BN = 128, BK = 32;
constexpr int KIT = Cdim / BK;     // 16 k-slabs

// ---------------- kernel2 smem layout ----------------
constexpr int AB_STR  = 80;                        // 64B data + 16B pad (ldmatrix conflict-free)
constexpr int STAGEB  = 128 * AB_STR;              // 10240 per tile buffer
constexpr int A_OFF   = 0;                         // 4 stages A
constexpr int B_OFF   = 4 * STAGEB;                // 4 stages B
constexpr int SMEM_BYTES = 8 * STAGEB;             // 81920 (2 CTAs/SM)

// intermediates built per launch
__device__ __half g_wpwh[Cdim * Cdim];             // fp16 w_pw
__device__ __half g_A[(size_t)Mrows * Cdim];       // fp16 dw output (32 MB)

// ---------------- helpers ----------------
static __device__ __forceinline__ uint32_t smem_u32(const void* p) {
    uint32_t a;
    asm("{ .reg .u64 t; cvta.to.shared.u64 t, %1; cvt.u32.u64 %0, t; }" : "=r"(a) : "l"(p));
    return a;
}
static __device__ __forceinline__ void cpa16(void* dst, const void* src) {
    uint32_t s = smem_u32(dst);
    asm volatile("cp.async.cg.shared.global [%0], [%1], 16;" :: "r"(s), "l"(src));
}
static __device__ __forceinline__ void ldmx4(uint32_t* r, uint32_t a) {
    asm volatile("ldmatrix.sync.aligned.m8n8.x4.shared.b16 {%0,%1,%2,%3}, [%4];"
                 : "=r"(r[0]), "=r"(r[1]), "=r"(r[2]), "=r"(r[3]) : "r"(a));
}
static __device__ __forceinline__ void hmma(float* c, const uint32_t* a,
                                            uint32_t b0, uint32_t b1) {
    asm volatile(
        "mma.sync.aligned.m16n8k16.row.col.f32.f16.f16.f32 "
        "{%0,%1,%2,%3},{%4,%5,%6,%7},{%8,%9},{%0,%1,%2,%3};"
        : "+f"(c[0]), "+f"(c[1]), "+f"(c[2]), "+f"(c[3])
        : "r"(a[0]), "r"(a[1]), "r"(a[2]), "r"(a[3]), "r"(b0), "r"(b1));
}
#define COMMIT asm volatile("cp.async.commit_group;" ::: "memory")

// ---------------- prep: w_pw fp32 -> fp16 ----------------
__global__ void prep_k(const float4* __restrict__ wpw) {
    int i = blockIdx.x * 256 + threadIdx.x;
    float4 v = wpw[i];
    __half2 h0 = __floats2half2_rn(v.x, v.y);
    __half2 h1 = __floats2half2_rn(v.z, v.w);
    uint2 u;
    u.x = *reinterpret_cast<uint32_t*>(&h0);
    u.y = *reinterpret_cast<uint32_t*>(&h1);
    *reinterpret_cast<uint2*>(g_wpwh + (size_t)i * 4) = u;
}

// ---------------- kernel 1: depthwise conv -> fp16 A ----------------
// thread: 4 channels x 16 consecutive rows, 5-row sliding window in registers.
__global__ void __launch_bounds__(256)
dw_k(const float* __restrict__ x,     // [B,L,C]
     const int*   __restrict__ segb,  // [B,S,2]
     const float* __restrict__ wdw,   // [C,K]
     const float* __restrict__ bdw)   // [C]
{
    const int tid = threadIdx.x;
    const int c0  = (tid & 127) * 4;
    const int g0  = blockIdx.x * 32 + (tid >> 7) * 16;   // first output row

    // segment starts for this batch row (starts[0] == 0 always)
    const int* sp = segb + (g0 >> 12) * 16;
    int st[7];
    #pragma unroll
    for (int s = 0; s < 7; s++) st[s] = sp[2 * (s + 1)];

    // depthwise weights + bias for 4 channels
    float4 wv[5];
    #pragma unroll
    for (int j = 0; j < 5; j++) {
        wv[j].x = wdw[(c0 + 0) * 5 + j];
        wv[j].y = wdw[(c0 + 1) * 5 + j];
        wv[j].z = wdw[(c0 + 2) * 5 + j];
        wv[j].w = wdw[(c0 + 3) * 5 + j];
    }
    const float4 bv = *(const float4*)(bdw + c0);

    // preload halo rows g0-4 .. g0-1 (clamped; masked via nt when invalid)
    float4 xw[5];
    #pragma unroll
    for (int d = 0; d < 4; d++) {
        int m = g0 - 4 + d; if (m < 0) m = 0;
        xw[d] = *(const float4*)(x + (size_t)m * Cdim + c0);
    }

    #pragma unroll
    for (int r = 0; r < 16; r++) {
        const int g = g0 + r;
        xw[(r + 4) % 5] = *(const float4*)(x + (size_t)g * Cdim + c0);
        const int l = g & 4095;
        int ss = 0;
        #pragma unroll
        for (int s = 0; s < 7; s++)
            if (st[s] <= l && st[s] > ss) ss = st[s];
        int nt = l - ss + 1; if (nt > 5) nt = 5;

        float4 a = bv;
        const float4 x0 = xw[(r + 4) % 5];
        a.x += wv[4].x * x0.x; a.y += wv[4].y * x0.y;
        a.z += wv[4].z * x0.z; a.w += wv[4].w * x0.w;
        if (nt > 1) { const float4 v = xw[(r + 3) % 5];
            a.x += wv[3].x * v.x; a.y += wv[3].y * v.y;
            a.z += wv[3].z * v.z; a.w += wv[3].w * v.w; }
        if (nt > 2) { const float4 v = xw[(r + 2) % 5];
            a.x += wv[2].x * v.x; a.y += wv[2].y * v.y;
            a.z += wv[2].z * v.z; a.w += wv[2].w * v.w; }
        if (nt > 3) { const float4 v = xw[(r + 1) % 5];
            a.x += wv[1].x * v.x; a.y += wv[1].y * v.y;
            a.z += wv[1].z * v.z; a.w += wv[1].w * v.w; }
        if (nt > 4) { const float4 v = xw[(r + 0) % 5];
            a.x += wv[0].x * v.x; a.y += wv[0].y * v.y;
            a.z += wv[0].z * v.z; a.w += wv[0].w * v.w; }

        __half2 h0 = __floats2half2_rn(a.x, a.y);
        __half2 h1 = __floats2half2_rn(a.z, a.w);
        uint2 u;
        u.x = *reinterpret_cast<uint32_t*>(&h0);
        u.y = *reinterpret_cast<uint32_t*>(&h1);
        *reinterpret_cast<uint2*>(g_A + (size_t)g * Cdim + c0) = u;
    }
}

// ---------------- kernel 2: fp16 GEMM, 4-stage cp.async pipeline ----------------
__global__ void __launch_bounds__(256, 2)
gemm_k(const float* __restrict__ bpw,   // [C]
       float*       __restrict__ out)   // [B,L,C]
{
    extern __shared__ char sm[];
    const uint32_t smb = smem_u32(sm);

    const int tid  = threadIdx.x;
    const int lane = tid & 31;
    const int warp = tid >> 5;
    const int wm   = (warp >> 2) * 64;
    const int wn   = (warp & 3) * 32;
    const int bx   = blockIdx.x;
    const int m0   = (bx >> 2) * BM;   // N-tile fastest: 4 CTAs share A rows via L2
    const int n0   = (bx & 3) * BN;

    auto load_slab = [&](int s) {
        if (s >= KIT) return;
        const int c0 = s * BK;
        char* ad = sm + A_OFF + (s & 3) * STAGEB;
        char* bd = sm + B_OFF + (s & 3) * STAGEB;
        #pragma unroll
        for (int q = 0; q < 2; q++) {
            int idx = tid + q * 256;
            int row = idx >> 2, ch = idx & 3;
            cpa16(ad + row * AB_STR + ch * 16,
                  g_A + (size_t)(m0 + row) * Cdim + c0 + ch * 8);
            cpa16(bd + row * AB_STR + ch * 16,
                  g_wpwh + (size_t)(n0 + row) * Cdim + c0 + ch * 8);
        }
    };

    float cacc[4][4][4];
    #pragma unroll
    for (int i = 0; i < 4; i++)
        #pragma unroll
        for (int j = 0; j < 4; j++)
            #pragma unroll
            for (int k = 0; k < 4; k++) cacc[i][j][k] = 0.f;

    auto mma_stage = [&](int it) {
        const uint32_t Ab = smb + A_OFF + (it & 3) * STAGEB;
        const uint32_t Bb = smb + B_OFF + (it & 3) * STAGEB;
        const uint32_t aaddr = Ab + (wm + (lane & 15)) * AB_STR + (lane >> 4) * 16;
        const uint32_t baddr = Bb + (wn + (lane & 7) + ((lane >> 4) & 1) * 8) * AB_STR
                             + ((lane >> 3) & 1) * 16;
        #pragma unroll
        for (int ks = 0; ks < 2; ks++) {
            uint32_t af[4][4], bf[2][4];
            #pragma unroll
            for (int mt = 0; mt < 4; mt++)
                ldmx4(af[mt], aaddr + mt * 16 * AB_STR + ks * 32);
            #pragma unroll
            for (int g = 0; g < 2; g++)
                ldmx4(bf[g], baddr + g * 16 * AB_STR + ks * 32);
            #pragma unroll
            for (int mt = 0; mt < 4; mt++)
                #pragma unroll
                for (int nt = 0; nt < 4; nt++)
                    hmma(cacc[mt][nt], af[mt],
                         bf[nt >> 1][(nt & 1) * 2 + 0],
                         bf[nt >> 1][(nt & 1) * 2 + 1]);
        }
    };

    // prologue: 3 slabs in flight
    load_slab(0); COMMIT;
    load_slab(1); COMMIT;
    load_slab(2); COMMIT;

    #pragma unroll 1
    for (int it = 0; it < KIT; it++) {
        asm volatile("cp.async.wait_group 2;" ::: "memory");  // slab it landed
        __syncthreads();                                      // + stage (it+3)&3 free
        load_slab(it + 3); COMMIT;                            // empty commit at tail
        mma_stage(it);
    }

    // epilogue: + b_pw, coalesced float2 stores
    float2* outv = (float2*)out;
    #pragma unroll
    for (int nt = 0; nt < 4; nt++) {
        int gn = n0 + wn + nt * 8 + (lane & 3) * 2;
        float2 bp = *(const float2*)(bpw + gn);
        #pragma unroll
        for (int mt = 0; mt < 4; mt++) {
            int gm = m0 + wm + mt * 16 + (lane >> 2);
            float2 v0 = { cacc[mt][nt][0] + bp.x, cacc[mt][nt][1] + bp.y };
            float2 v1 = { cacc[mt][nt][2] + bp.x, cacc[mt][nt][3] + bp.y };
            outv[((size_t)gm * Cdim + gn) >> 1]       = v0;
            outv[(((size_t)gm + 8) * Cdim + gn) >> 1] = v1;
        }
    }
}

extern "C" void kernel_launch(void* const* d_in, const int* in_sizes, int n_in,
                              void* d_out, int out_size) {
    const float* x    = (const float*)d_in[0];
    const int*   segb = (const int*)  d_in[1];
    const float* wdw  = (const float*)d_in[2];
    const float* bdw  = (const float*)d_in[3];
    const float* wpw  = (const float*)d_in[4];
    const float* bpw  = (const float*)d_in[5];
    float* out = (float*)d_out;

    prep_k<<<Cdim * Cdim / 4 / 256, 256>>>((const float4*)wpw);
    dw_k<<<Mrows / 32, 256>>>(x, segb, wdw, bdw);

    cudaFuncSetAttribute(gemm_k,
                         cudaFuncAttributeMaxDynamicSharedMemorySize, SMEM_BYTES);
    dim3 grid((Mrows / BM) * (Cdim / BN));   // 1024 CTAs
    gemm_k<<<grid, 256, SMEM_BYTES>>>(bpw, out);
}